// round 1
// baseline (speedup 1.0000x reference)
#include <cuda_runtime.h>
#include <math.h>
#include <stdint.h>

#define D_DATES 2048
#define NSLOTS  (2 * D_DATES)   // per (date, label) slots
#define NBLK    304             // 2 CTAs per SM on 152-SM GB300
#define BLK     1024
#define E5      148.4131591025766f

// Scratch (static __device__ — no allocations allowed)
__device__ unsigned long long g_slots[NBLK * NSLOTS];   // ~9.7 MB
__device__ double       g_vol_sum[NBLK];
__device__ unsigned int g_vol_cnt[NBLK];
__device__ unsigned int g_cnt_tot[NSLOTS];
__device__ float        g_sp1_tot[NSLOTS];
__device__ float        g_sexp_tot[NSLOTS];

// ---------------------------------------------------------------------------
// K1: single fused pass over B elements.
//  - QLIKE vol loss: register accumulation -> per-block scratch (no atomics)
//  - Per-(date,label) stats: ONE packed 64-bit shared atomic per element.
//    Packing (per-block maxima, ~28 elems/slot/block expected, <<256):
//      bits [0:12)  count            (<= 4095)
//      bits [12:38) sum(p1 * 2^16)   (<= 256*65535  ~= 2^24)
//      bits [38:64) sum(e^p1 * 2^15) (<= 256*89100  ~= 2^24.5)
// ---------------------------------------------------------------------------
__global__ void __launch_bounds__(BLK, 2)
k1_main(const float2* __restrict__ logits,
        const int*    __restrict__ labels,
        const float*  __restrict__ vpred,
        const float*  __restrict__ vtgt,
        const int*    __restrict__ dates,
        int B)
{
    __shared__ unsigned long long s_slots[NSLOTS];   // 32 KB
    __shared__ float    s_vf[BLK / 32];
    __shared__ unsigned s_vu[BLK / 32];

    const int tid = threadIdx.x;
    for (int i = tid; i < NSLOTS; i += BLK) s_slots[i] = 0ull;
    __syncthreads();

    float    vol_acc = 0.0f;
    unsigned vol_n   = 0;

    const int stride = gridDim.x * BLK;
    for (int i = blockIdx.x * BLK + tid; i < B; i += stride) {
        // ---- volatility QLIKE ----
        float p = vpred[i];
        float t = vtgt[i];
        bool vv = (t == t) && (t > 1e-6f) && (p > 1e-6f);
        if (vv) {
            float pv = fmaxf(p * p, 1e-6f);
            float tv = fmaxf(t * t, 1e-6f);
            vol_acc += tv / pv + __logf(pv);
            vol_n++;
        }

        // ---- direction: per-(date,label) stats ----
        int lab = labels[i];
        if (lab >= 0) {
            float2 lg = logits[i];
            // p1 = softmax(logits)[1] = sigmoid(l1 - l0)
            float p1 = 1.0f / (1.0f + __expf(lg.x - lg.y));
            unsigned up = (unsigned)(p1 * 65536.0f);
            if (up > 65535u) up = 65535u;
            float p1q = (float)up * (1.0f / 65536.0f);
            float e   = __expf(p1q);                 // in (1, e)
            unsigned ue = (unsigned)rintf(e * 32768.0f);
            int d = dates[i];
            int slot = (d << 1) | (lab > 0 ? 1 : 0);
            unsigned long long v = 1ull
                                 | ((unsigned long long)up << 12)
                                 | ((unsigned long long)ue << 38);
            atomicAdd(&s_slots[slot], v);
        }
    }

    // ---- warp-level vol reduction ----
    #pragma unroll
    for (int o = 16; o; o >>= 1) {
        vol_acc += __shfl_down_sync(0xFFFFFFFFu, vol_acc, o);
        vol_n   += __shfl_down_sync(0xFFFFFFFFu, vol_n,   o);
    }
    const int wid  = tid >> 5;
    const int lane = tid & 31;
    if (lane == 0) { s_vf[wid] = vol_acc; s_vu[wid] = vol_n; }

    __syncthreads();   // atomics done + s_vf ready

    // ---- flush slot table (plain coalesced stores, no global atomics) ----
    unsigned long long* dst = &g_slots[(size_t)blockIdx.x * NSLOTS];
    for (int i = tid; i < NSLOTS; i += BLK) dst[i] = s_slots[i];

    // ---- block-level vol reduction (warp 0) ----
    if (wid == 0) {
        double   a = (lane < BLK / 32) ? (double)s_vf[lane] : 0.0;
        unsigned n = (lane < BLK / 32) ? s_vu[lane] : 0u;
        #pragma unroll
        for (int o = 16; o; o >>= 1) {
            a += __shfl_down_sync(0xFFFFFFFFu, a, o);
            n += __shfl_down_sync(0xFFFFFFFFu, n, o);
        }
        if (lane == 0) { g_vol_sum[blockIdx.x] = a; g_vol_cnt[blockIdx.x] = n; }
    }
}

// ---------------------------------------------------------------------------
// K2: reduce per-block slot tables -> per-slot totals (coalesced, no atomics)
// ---------------------------------------------------------------------------
__global__ void k2_reduce(int nblk)
{
    int s = blockIdx.x * blockDim.x + threadIdx.x;
    if (s >= NSLOTS) return;
    unsigned c = 0;
    unsigned long long sp1 = 0, sexp = 0;
    for (int b = 0; b < nblk; b++) {
        unsigned long long v = g_slots[(size_t)b * NSLOTS + s];
        c    += (unsigned)(v & 0xFFFull);
        sp1  += (v >> 12) & 0x3FFFFFFull;
        sexp += (v >> 38);
    }
    g_cnt_tot[s]  = c;
    g_sp1_tot[s]  = (float)((double)sp1  * (1.0 / 65536.0));
    g_sexp_tot[s] = (float)((double)sexp * (1.0 / 32768.0));
}

// ---------------------------------------------------------------------------
// K3: final — per-date CE + include gating + vol finalize + combine.
//   ce_date = log(pden) - (e5*S1 + S0) / (n1*e5 + n0)
// ---------------------------------------------------------------------------
__global__ void __launch_bounds__(1024)
k3_final(float* __restrict__ out, int out_size, int nblk)
{
    __shared__ double   s_ce[32];
    __shared__ int      s_nd[32];
    __shared__ double   s_vs[32];
    __shared__ unsigned s_vn[32];

    const int tid = threadIdx.x;
    double ce_acc = 0.0;
    int    nd     = 0;
    for (int d = tid; d < D_DATES; d += 1024) {
        unsigned c0 = g_cnt_tot[2 * d];
        unsigned c1 = g_cnt_tot[2 * d + 1];
        unsigned nv = c0 + c1;
        if (nv >= 2) {
            float pden = g_sexp_tot[2 * d] + g_sexp_tot[2 * d + 1];
            float tden = (float)c1 * E5 + (float)c0;
            float dot  = (E5 * g_sp1_tot[2 * d + 1] + g_sp1_tot[2 * d]) / tden;
            ce_acc += (double)(logf(pden) - dot);
            nd++;
        }
    }
    double   vs = 0.0;
    unsigned vn = 0;
    for (int b = tid; b < nblk; b += 1024) { vs += g_vol_sum[b]; vn += g_vol_cnt[b]; }

    // block reduction
    #pragma unroll
    for (int o = 16; o; o >>= 1) {
        ce_acc += __shfl_down_sync(0xFFFFFFFFu, ce_acc, o);
        nd     += __shfl_down_sync(0xFFFFFFFFu, nd, o);
        vs     += __shfl_down_sync(0xFFFFFFFFu, vs, o);
        vn     += __shfl_down_sync(0xFFFFFFFFu, vn, o);
    }
    const int wid = tid >> 5, lane = tid & 31;
    if (lane == 0) { s_ce[wid] = ce_acc; s_nd[wid] = nd; s_vs[wid] = vs; s_vn[wid] = vn; }
    __syncthreads();
    if (wid == 0) {
        double   ce = (lane < 32) ? s_ce[lane] : 0.0;
        int      n  = (lane < 32) ? s_nd[lane] : 0;
        double   v  = (lane < 32) ? s_vs[lane] : 0.0;
        unsigned vc = (lane < 32) ? s_vn[lane] : 0u;
        #pragma unroll
        for (int o = 16; o; o >>= 1) {
            ce += __shfl_down_sync(0xFFFFFFFFu, ce, o);
            n  += __shfl_down_sync(0xFFFFFFFFu, n,  o);
            v  += __shfl_down_sync(0xFFFFFFFFu, v,  o);
            vc += __shfl_down_sync(0xFFFFFFFFu, vc, o);
        }
        if (lane == 0) {
            float vol_loss = (vc > 0u) ? (float)(v / (double)vc) : 0.0f;
            int   ndiv     = n > 1 ? n : 1;
            float dir_loss = (float)(ce / (double)ndiv);
            float total    = 0.85f * vol_loss + 0.15f * dir_loss;
            out[0] = total;
            if (out_size > 1) out[1] = vol_loss;
            if (out_size > 2) out[2] = dir_loss;
        }
    }
}

// ---------------------------------------------------------------------------
extern "C" void kernel_launch(void* const* d_in, const int* in_sizes, int n_in,
                              void* d_out, int out_size)
{
    const float2* logits = (const float2*)d_in[0];
    const int*    labels = (const int*)d_in[1];
    const float*  vpred  = (const float*)d_in[2];
    const float*  vtgt   = (const float*)d_in[3];
    const int*    dates  = (const int*)d_in[4];
    const int B = in_sizes[1];

    k1_main<<<NBLK, BLK>>>(logits, labels, vpred, vtgt, dates, B);
    k2_reduce<<<NSLOTS / 128, 128>>>(NBLK);
    k3_final<<<1, 1024>>>((float*)d_out, out_size, NBLK);
}